// round 15
// baseline (speedup 1.0000x reference)
#include <cuda_runtime.h>
#include <cuda_fp16.h>
#include <cstdint>
#include <math.h>

// Problem constants
#define BB   2
#define TT   2048
#define DD   2048
#define HH   32
#define KVH  8
#define HD   64
#define MTOT (BB*TT)      // 4096
#define DKV  (KVH*HD)     // 512
#define NQKV (DD + 2*DKV) // 3072

// ---------------------------------------------------------------------------
// Scratch (__device__ globals; no allocation allowed) — all single fp16
// ---------------------------------------------------------------------------
__device__ __half g_x[(size_t)MTOT * DD];
__device__ __half g_Wqkv[(size_t)NQKV * DD];           // [Wq; Wk; Wv]
__device__ __half g_Wo[(size_t)DD * DD];

__device__ __half g_Q[(size_t)MTOT * DD];
__device__ __half g_K[(size_t)MTOT * DKV];
__device__ __half g_V[(size_t)MTOT * DKV];
__device__ __half g_A[(size_t)MTOT * DD];

// ---------------------------------------------------------------------------
// Helpers (portable PTX only: cp.async / ldmatrix / mma.sync)
// ---------------------------------------------------------------------------
__device__ __forceinline__ uint32_t s2u(const void* p) {
    return (uint32_t)__cvta_generic_to_shared(p);
}

#define CP16(sa, ga) \
    asm volatile("cp.async.cg.shared.global [%0], [%1], 16;" :: "r"(sa), "l"(ga) : "memory")
#define CPCOMMIT()  asm volatile("cp.async.commit_group;" ::: "memory")
#define CPWAIT(n)   asm volatile("cp.async.wait_group %0;" :: "n"(n) : "memory")

#define LDSM4(r0, r1, r2, r3, addr) \
    asm volatile("ldmatrix.sync.aligned.m8n8.x4.shared.b16 {%0,%1,%2,%3}, [%4];" \
        : "=r"(r0), "=r"(r1), "=r"(r2), "=r"(r3) : "r"(addr))

#define LDSM4T(r0, r1, r2, r3, addr) \
    asm volatile("ldmatrix.sync.aligned.m8n8.x4.trans.shared.b16 {%0,%1,%2,%3}, [%4];" \
        : "=r"(r0), "=r"(r1), "=r"(r2), "=r"(r3) : "r"(addr))

// fp16 mma, b from array
#define MMAH16816(d, a, b) \
    asm volatile("mma.sync.aligned.m16n8k16.row.col.f32.f16.f16.f32 " \
        "{%0,%1,%2,%3}, {%4,%5,%6,%7}, {%8,%9}, {%0,%1,%2,%3};" \
        : "+f"((d)[0]), "+f"((d)[1]), "+f"((d)[2]), "+f"((d)[3]) \
        : "r"((a)[0]), "r"((a)[1]), "r"((a)[2]), "r"((a)[3]), "r"((b)[0]), "r"((b)[1]))

// fp16 mma, b from scalars
#define MMAH16816R(d, a, b0v, b1v) \
    asm volatile("mma.sync.aligned.m16n8k16.row.col.f32.f16.f16.f32 " \
        "{%0,%1,%2,%3}, {%4,%5,%6,%7}, {%8,%9}, {%0,%1,%2,%3};" \
        : "+f"((d)[0]), "+f"((d)[1]), "+f"((d)[2]), "+f"((d)[3]) \
        : "r"((a)[0]), "r"((a)[1]), "r"((a)[2]), "r"((a)[3]), "r"(b0v), "r"(b1v))

// 128B-row swizzle
__device__ __forceinline__ uint32_t sw128(uint32_t base, int row, int chunk) {
    return base + row * 128 + ((chunk ^ (row & 7)) << 4);
}

__device__ __forceinline__ uint32_t pack_h2(float x0, float x1) {
    __half2 p = __halves2half2(__float2half_rn(x0), __float2half_rn(x1));
    return *(uint32_t*)&p;
}

// ---------------------------------------------------------------------------
// Merged fp32 -> fp16 convert kernel: all 5 regions in one launch.
// ---------------------------------------------------------------------------
#define NQ_X  (MTOT * DD / 4)
#define NQ_WQ (DD * DD / 4)
#define NQ_WK (DKV * DD / 4)
#define NQ_ALL (NQ_X + NQ_WQ + 2 * NQ_WK + NQ_WQ)

__global__ __launch_bounds__(256)
void conv_all_kernel(const float* __restrict__ x,  const float* __restrict__ Wq,
                     const float* __restrict__ Wk, const float* __restrict__ Wv,
                     const float* __restrict__ Wo,
                     __half* __restrict__ xh, __half* __restrict__ wqkv,
                     __half* __restrict__ wo)
{
    int i = blockIdx.x * blockDim.x + threadIdx.x;
    if (i >= NQ_ALL) return;
    const float* src;
    __half* dst;
    int j = i;
    if (j < NQ_X)                 { src = x;  dst = xh; }
    else if ((j -= NQ_X) < NQ_WQ) { src = Wq; dst = wqkv; }
    else if ((j -= NQ_WQ) < NQ_WK){ src = Wk; dst = wqkv + (size_t)DD * DD; }
    else if ((j -= NQ_WK) < NQ_WK){ src = Wv; dst = wqkv + (size_t)(DD + DKV) * DD; }
    else { j -= NQ_WK;             src = Wo; dst = wo; }
    float4 v = ((const float4*)src)[j];
    ((uint2*)dst)[j] = make_uint2(pack_h2(v.x, v.y), pack_h2(v.z, v.w));
}

// ---------------------------------------------------------------------------
// fp16 1-pass GEMM:  C = A * B^T   (R13 form — no frag double-buffer)
// CTA 128x128, BK=64, 3-stage cp.async (96KB), one barrier per chunk.
// 256 threads = 8 warps (2x4), warp tile 64x32.
// __launch_bounds__(256, 2): 128-reg cap, 2 CTAs/SM.
// ---------------------------------------------------------------------------
#define GSTAGES   3
#define GTILE_B   16384
#define GSTAGE_B  (2 * GTILE_B)             // 32 KB
#define GEMM_SMEM (GSTAGES * GSTAGE_B)      // 96 KB

template<int MODE>
__global__ __launch_bounds__(256, 2)
void gemm_tc_kernel(const __half* __restrict__ Ah, const __half* __restrict__ Bh,
                    float* __restrict__ C,
                    __half* __restrict__ Qo, __half* __restrict__ Ko, __half* __restrict__ Vo,
                    int M, int N, int K)
{
    extern __shared__ __align__(128) char smem[];
    const uint32_t sbase = s2u(smem);

    const int tid = threadIdx.x;
    const int wid = tid >> 5;
    const int lane = tid & 31;
    const int bm = blockIdx.y * 128;
    const int bn = blockIdx.x * 128;

    const int wm = (wid & 1) * 64;
    const int wn = (wid >> 1) * 32;

    const size_t rowstride = (size_t)K * 2;
    const int NC = K >> 6;

    auto load_chunk = [&](int c, int s) {
        const uint32_t sb = sbase + s * GSTAGE_B;
        const size_t k0b = (size_t)c * 128;
#pragma unroll
        for (int t = 0; t < 2; t++) {
            const int rbase = t ? bn : bm;
            const char* src = (const char*)(t ? Bh : Ah);
#pragma unroll
            for (int j = 0; j < 4; j++) {
                int i = tid + j * 256;
                int r = i >> 3;
                int ck = i & 7;
                const char* ga = src + (size_t)(rbase + r) * rowstride + k0b + ck * 16;
                CP16(sw128(sb + t * GTILE_B, r, ck), ga);
            }
        }
    };

    float acc[4][4][4];
#pragma unroll
    for (int i = 0; i < 4; i++)
#pragma unroll
        for (int j = 0; j < 4; j++)
#pragma unroll
            for (int q = 0; q < 4; q++) acc[i][j][q] = 0.f;

    load_chunk(0, 0); CPCOMMIT();
    load_chunk(1, 1); CPCOMMIT();

    for (int c = 0; c < NC; c++) {
        const int s = c % GSTAGES;
        CPWAIT(1);
        __syncthreads();

        if (c + 2 < NC) {
            load_chunk(c + 2, (c + 2) % GSTAGES);
            CPCOMMIT();
        }

        const uint32_t sA = sbase + s * GSTAGE_B;
        const uint32_t sB = sA + GTILE_B;

#pragma unroll
        for (int ks = 0; ks < 4; ks++) {
            uint32_t af[4][4], bf[4][2];
            {
                int ar = (lane & 15);
                int ac = 2 * ks + (lane >> 4);
#pragma unroll
                for (int fm = 0; fm < 4; fm++) {
                    uint32_t ad = sw128(sA, wm + fm * 16 + ar, ac);
                    LDSM4(af[fm][0], af[fm][1], af[fm][2], af[fm][3], ad);
                }
                int br = (lane & 7);
                int bsel = (lane >> 4);
                int bc = 2 * ks + ((lane >> 3) & 1);
#pragma unroll
                for (int fp = 0; fp < 2; fp++) {
                    uint32_t bd = sw128(sB, wn + (fp * 2 + bsel) * 8 + br, bc);
                    uint32_t t0, t1, t2, t3;
                    LDSM4(t0, t1, t2, t3, bd);
                    bf[fp * 2][0] = t0; bf[fp * 2][1] = t1;
                    bf[fp * 2 + 1][0] = t2; bf[fp * 2 + 1][1] = t3;
                }
            }

#pragma unroll
            for (int fm = 0; fm < 4; fm++)
#pragma unroll
                for (int fn = 0; fn < 4; fn++)
                    MMAH16816(acc[fm][fn], af[fm], bf[fn]);
        }
    }

    const int lr = lane >> 2;
    const int lc = (lane & 3) * 2;
#pragma unroll
    for (int fm = 0; fm < 4; fm++) {
#pragma unroll
        for (int fn = 0; fn < 4; fn++) {
            int r0 = bm + wm + fm * 16 + lr;
            int cc = bn + wn + fn * 8 + lc;
            if (MODE == 0) {
                if (bn < DD) {
                    *(uint32_t*)&Qo[(size_t)r0 * DD + cc] =
                        pack_h2(acc[fm][fn][0], acc[fm][fn][1]);
                    *(uint32_t*)&Qo[(size_t)(r0 + 8) * DD + cc] =
                        pack_h2(acc[fm][fn][2], acc[fm][fn][3]);
                } else if (bn < DD + DKV) {
                    int kc = cc - DD;
                    *(uint32_t*)&Ko[(size_t)r0 * DKV + kc] =
                        pack_h2(acc[fm][fn][0], acc[fm][fn][1]);
                    *(uint32_t*)&Ko[(size_t)(r0 + 8) * DKV + kc] =
                        pack_h2(acc[fm][fn][2], acc[fm][fn][3]);
                } else {
                    int vc = cc - DD - DKV;
                    *(uint32_t*)&Vo[(size_t)r0 * DKV + vc] =
                        pack_h2(acc[fm][fn][0], acc[fm][fn][1]);
                    *(uint32_t*)&Vo[(size_t)(r0 + 8) * DKV + vc] =
                        pack_h2(acc[fm][fn][2], acc[fm][fn][3]);
                }
            } else {
                *(float2*)&C[(size_t)r0 * N + cc]       = make_float2(acc[fm][fn][0], acc[fm][fn][1]);
                *(float2*)&C[(size_t)(r0 + 8) * N + cc] = make_float2(acc[fm][fn][2], acc[fm][fn][3]);
            }
        }
    }
}

// ---------------------------------------------------------------------------
// Tensor-core flash attention (fp16 1-pass).
// LPT scheduling: qt = (T/128 - 1) - blockIdx.x so heavy (large-qt) tiles
// launch first and light tiles pack the tail wave.
// __launch_bounds__(256, 2). 8 warps x 16 q-rows. KV tile 64, 3-stage ring.
// ---------------------------------------------------------------------------
#define QTILE_B   16384
#define KVSUB_B   8192
#define FSTAGE_B  (2 * KVSUB_B)
#define FSTAGES   3
#define FLASH_SMEM (QTILE_B + FSTAGES * FSTAGE_B)

__global__ __launch_bounds__(256, 2)
void flash_tc_kernel()
{
    extern __shared__ __align__(128) char fsm[];
    const uint32_t sbase = s2u(fsm);
    const uint32_t QT = sbase;
    const uint32_t STG0 = sbase + QTILE_B;

    const int qt  = (TT / 128 - 1) - blockIdx.x;   // heavy tiles first
    const int h   = blockIdx.y;
    const int b   = blockIdx.z;
    const int kvh = h >> 2;
    const int qb  = qt * 128;

    const int tid = threadIdx.x;
    const int wid = tid >> 5;
    const int lane = tid & 31;

    // ---- load Q tile ----
#pragma unroll
    for (int j = 0; j < 4; j++) {
        int i = tid + j * 256;
        int r = i >> 3;
        int ck = i & 7;
        size_t e = (size_t)(b * TT + qb + r) * DD + h * HD + ck * 8;
        CP16(sw128(QT, r, ck), (const char*)&g_Q[e]);
    }
    CPCOMMIT();

    auto load_kv = [&](int kt, int s) {
        const uint32_t sb = STG0 + s * FSTAGE_B;
#pragma unroll
        for (int j = 0; j < 2; j++) {
            int i = tid + j * 256;
            int r = i >> 3;
            int ck = i & 7;
            size_t e = (size_t)(b * TT + kt * 64 + r) * DKV + kvh * HD + ck * 8;
            uint32_t so = sw128(sb, r, ck);
            CP16(so,           (const char*)&g_K[e]);
            CP16(so + KVSUB_B, (const char*)&g_V[e]);
        }
    };

    const int NT = 2 * (qt + 1);

    load_kv(0, 0); CPCOMMIT();
    if (NT > 1) { load_kv(1, 1); CPCOMMIT(); }

    CPWAIT(2);
    __syncthreads();

    // ---- Q fragments (register-resident) ----
    uint32_t qF[4][4];
    {
        int ar = lane & 15;
        int ac = lane >> 4;
#pragma unroll
        for (int ks = 0; ks < 4; ks++) {
            uint32_t ad = sw128(QT, wid * 16 + ar, 2 * ks + ac);
            LDSM4(qF[ks][0], qF[ks][1], qF[ks][2], qF[ks][3], ad);
        }
    }

    float oacc[8][4];
#pragma unroll
    for (int i = 0; i < 8; i++)
#pragma unroll
        for (int q = 0; q < 4; q++) oacc[i][q] = 0.f;
    float mrow[2] = {-1e30f, -1e30f};
    float lrow[2] = {0.f, 0.f};

    const int wr = qb + wid * 16;
    const float scale = 0.125f;

    for (int kt = 0; kt < NT; kt++) {
        const int s = kt % FSTAGES;
        const int kb = kt * 64;

        CPWAIT(1);
        __syncthreads();

        if (kt + 2 < NT) {
            load_kv(kt + 2, (kt + 2) % FSTAGES);
            CPCOMMIT();
        }

        const uint32_t KH = STG0 + s * FSTAGE_B;
        const uint32_t VH = KH + KVSUB_B;

        // ---- S = Q K^T ----
        float sacc[8][4];
#pragma unroll
        for (int i = 0; i < 8; i++)
#pragma unroll
            for (int q = 0; q < 4; q++) sacc[i][q] = 0.f;

        {
            int br = lane & 7;
            int bsel = lane >> 4;
            int bksel = (lane >> 3) & 1;
#pragma unroll
            for (int ks = 0; ks < 4; ks++) {
                int bc = 2 * ks + bksel;
#pragma unroll
                for (int fp = 0; fp < 4; fp++) {
                    int krow = fp * 16 + bsel * 8 + br;
                    uint32_t t0, t1, t2, t3;
                    LDSM4(t0, t1, t2, t3, sw128(KH, krow, bc));
                    MMAH16816R(sacc[2 * fp],     qF[ks], t0, t1);
                    MMAH16816R(sacc[2 * fp + 1], qF[ks], t2, t3);
                }
            }
        }

        // ---- scale + causal mask ----
        const bool need_mask = (kb + 63 > wr);
#pragma unroll
        for (int fn = 0; fn < 8; fn++)
#pragma unroll
            for (int q = 0; q < 4; q++) sacc[fn][q] *= scale;
        if (need_mask) {
#pragma unroll
            for (int fn = 0; fn < 8; fn++)
#pragma unroll
                for (int q = 0; q < 4; q++) {
                    int kc = kb + fn * 8 + (lane & 3) * 2 + (q & 1);
                    int qr = wr + (lane >> 2) + (q >> 1) * 8;
                    if (kc > qr) sacc[fn][q] = -1e30f;
                }
        }

        // ---- online softmax ----
#pragma unroll
        for (int r = 0; r < 2; r++) {
            float rmax = -1e30f;
#pragma unroll
            for (int fn = 0; fn < 8; fn++) {
                rmax = fmaxf(rmax, sacc[fn][2 * r]);
                rmax = fmaxf(rmax, sacc[fn][2 * r + 1]);
            }
            rmax = fmaxf(rmax, __shfl_xor_sync(0xffffffffu, rmax, 1));
            rmax = fmaxf(rmax, __shfl_xor_sync(0xffffffffu, rmax, 2));

            float mn = fmaxf(mrow[r], rmax);
            float alpha = __expf(mrow[r] - mn);
            mrow[r] = mn;

            float rs = 0.f;
#pragma unroll
            for (int fn = 0; fn < 8; fn++) {
                float p0 = __expf(sacc[fn][2 * r] - mn);
                float p1 = __expf(sacc[fn][2 * r + 1] - mn);
                sacc[fn][2 * r] = p0;
                sacc[fn][2 * r + 1] = p1;
                rs += p0 + p1;
            }
            rs += __shfl_xor_sync(0xffffffffu, rs, 1);
            rs += __shfl_xor_sync(0xffffffffu, rs, 2);
            lrow[r] = lrow[r] * alpha + rs;

#pragma unroll
            for (int fn = 0; fn < 8; fn++) {
                oacc[fn][2 * r]     *= alpha;
                oacc[fn][2 * r + 1] *= alpha;
            }
        }

        // ---- O += P V ----
        {
            int g = lane >> 3;
            int vr_off = (g & 1) * 8 + (lane & 7);
            int vc_off = g >> 1;
#pragma unroll
            for (int ks = 0; ks < 4; ks++) {
                uint32_t pF[4];
                pF[0] = pack_h2(sacc[2 * ks][0],     sacc[2 * ks][1]);
                pF[1] = pack_h2(sacc[2 * ks][2],     sacc[2 * ks][3]);
                pF[2] = pack_h2(sacc[2 * ks + 1][0], sacc[2 * ks + 1][1]);
                pF[3] = pack_h2(sacc[2 * ks + 1][2], sacc[2 * ks + 1][3]);

                int vrow = ks * 16 + vr_off;
#pragma unroll
                for (int fv = 0; fv < 4; fv++) {
                    int vchunk = 2 * fv + vc_off;
                    uint32_t t0, t1, t2, t3;
                    LDSM4T(t0, t1, t2, t3, sw128(VH, vrow, vchunk));
                    MMAH16816R(oacc[2 * fv],     pF, t0, t1);
                    MMAH16816R(oacc[2 * fv + 1], pF, t2, t3);
                }
            }
        }
    }

    // ---- epilogue: normalize, fp16 store ----
#pragma unroll
    for (int r = 0; r < 2; r++) {
        float inv = 1.f / lrow[r];
        int row = wr + (lane >> 2) + 8 * r;
#pragma unroll
        for (int fn = 0; fn < 8; fn++) {
            int col = h * HD + fn * 8 + (lane & 3) * 2;
            float x0 = oacc[fn][2 * r] * inv;
            float x1 = oacc[fn][2 * r + 1] * inv;
            size_t e = (size_t)(b * TT + row) * DD + col;
            *(uint32_t*)&g_A[e] = pack_h2(x0, x1);
        }
    }
}

// ---------------------------------------------------------------------------
// Launch
// ---------------------------------------------------------------------------
extern "C" void kernel_launch(void* const* d_in, const int* in_sizes, int n_in,
                              void* d_out, int out_size)
{
    const float* x  = (const float*)d_in[0];
    const float* Wq = (const float*)d_in[1];
    const float* Wk = (const float*)d_in[2];
    const float* Wv = (const float*)d_in[3];
    const float* Wo = (const float*)d_in[4];
    float* out = (float*)d_out;

    __half *xh, *wqkv, *wo, *qh, *kh, *vh, *ah;
    cudaGetSymbolAddress((void**)&xh, g_x);
    cudaGetSymbolAddress((void**)&wqkv, g_Wqkv);
    cudaGetSymbolAddress((void**)&wo, g_Wo);
    cudaGetSymbolAddress((void**)&qh, g_Q);
    cudaGetSymbolAddress((void**)&kh, g_K);
    cudaGetSymbolAddress((void**)&vh, g_V);
    cudaGetSymbolAddress((void**)&ah, g_A);

    cudaFuncSetAttribute(gemm_tc_kernel<0>,
                         cudaFuncAttributeMaxDynamicSharedMemorySize, GEMM_SMEM);
    cudaFuncSetAttribute(gemm_tc_kernel<1>,
                         cudaFuncAttributeMaxDynamicSharedMemorySize, GEMM_SMEM);
    cudaFuncSetAttribute(flash_tc_kernel,
                         cudaFuncAttributeMaxDynamicSharedMemorySize, FLASH_SMEM);

    // Merged fp32 -> fp16 converts (one launch)
    conv_all_kernel<<<(NQ_ALL + 255) / 256, 256>>>(x, Wq, Wk, Wv, Wo, xh, wqkv, wo);

    // Merged QKV projection (fp16 1-pass, BK=64, 64x32 warp tiles, 2 CTAs/SM)
    gemm_tc_kernel<0><<<dim3(NQKV / 128, MTOT / 128), 256, GEMM_SMEM>>>(
        xh, wqkv, nullptr, qh, kh, vh, MTOT, NQKV, DD);

    // fp16 1-pass causal GQA flash attention (LPT order, 2 CTAs/SM)
    flash_tc_kernel<<<dim3(TT / 128, HH, BB), 256, FLASH_SMEM>>>();

    // Output projection (fp16 1-pass, BK=64, 64x32 warp tiles, 2 CTAs/SM)
    gemm_tc_kernel<1><<<dim3(DD / 128, MTOT / 128), 256, GEMM_SMEM>>>(
        ah, wo, out, nullptr, nullptr, nullptr, MTOT, DD, DD);
}

// round 16
// speedup vs baseline: 1.5227x; 1.5227x over previous
#include <cuda_runtime.h>
#include <cuda_fp16.h>
#include <cstdint>
#include <math.h>

// Problem constants
#define BB   2
#define TT   2048
#define DD   2048
#define HH   32
#define KVH  8
#define HD   64
#define MTOT (BB*TT)      // 4096
#define DKV  (KVH*HD)     // 512
#define NQKV (DD + 2*DKV) // 3072

// ---------------------------------------------------------------------------
// Scratch (__device__ globals; no allocation allowed) — all single fp16
// ---------------------------------------------------------------------------
__device__ __half g_x[(size_t)MTOT * DD];
__device__ __half g_Wqkv[(size_t)NQKV * DD];           // [Wq; Wk; Wv]
__device__ __half g_Wo[(size_t)DD * DD];

__device__ __half g_Q[(size_t)MTOT * DD];
__device__ __half g_K[(size_t)MTOT * DKV];
__device__ __half g_V[(size_t)MTOT * DKV];
__device__ __half g_A[(size_t)MTOT * DD];

// ---------------------------------------------------------------------------
// Helpers (portable PTX only: cp.async / ldmatrix / mma.sync)
// ---------------------------------------------------------------------------
__device__ __forceinline__ uint32_t s2u(const void* p) {
    return (uint32_t)__cvta_generic_to_shared(p);
}

#define CP16(sa, ga) \
    asm volatile("cp.async.cg.shared.global [%0], [%1], 16;" :: "r"(sa), "l"(ga) : "memory")
#define CPCOMMIT()  asm volatile("cp.async.commit_group;" ::: "memory")
#define CPWAIT(n)   asm volatile("cp.async.wait_group %0;" :: "n"(n) : "memory")

#define LDSM4(r0, r1, r2, r3, addr) \
    asm volatile("ldmatrix.sync.aligned.m8n8.x4.shared.b16 {%0,%1,%2,%3}, [%4];" \
        : "=r"(r0), "=r"(r1), "=r"(r2), "=r"(r3) : "r"(addr))

#define LDSM4T(r0, r1, r2, r3, addr) \
    asm volatile("ldmatrix.sync.aligned.m8n8.x4.trans.shared.b16 {%0,%1,%2,%3}, [%4];" \
        : "=r"(r0), "=r"(r1), "=r"(r2), "=r"(r3) : "r"(addr))

// fp16 mma, b from array
#define MMAH16816(d, a, b) \
    asm volatile("mma.sync.aligned.m16n8k16.row.col.f32.f16.f16.f32 " \
        "{%0,%1,%2,%3}, {%4,%5,%6,%7}, {%8,%9}, {%0,%1,%2,%3};" \
        : "+f"((d)[0]), "+f"((d)[1]), "+f"((d)[2]), "+f"((d)[3]) \
        : "r"((a)[0]), "r"((a)[1]), "r"((a)[2]), "r"((a)[3]), "r"((b)[0]), "r"((b)[1]))

// fp16 mma, b from scalars
#define MMAH16816R(d, a, b0v, b1v) \
    asm volatile("mma.sync.aligned.m16n8k16.row.col.f32.f16.f16.f32 " \
        "{%0,%1,%2,%3}, {%4,%5,%6,%7}, {%8,%9}, {%0,%1,%2,%3};" \
        : "+f"((d)[0]), "+f"((d)[1]), "+f"((d)[2]), "+f"((d)[3]) \
        : "r"((a)[0]), "r"((a)[1]), "r"((a)[2]), "r"((a)[3]), "r"(b0v), "r"(b1v))

// 128B-row swizzle
__device__ __forceinline__ uint32_t sw128(uint32_t base, int row, int chunk) {
    return base + row * 128 + ((chunk ^ (row & 7)) << 4);
}

__device__ __forceinline__ uint32_t pack_h2(float x0, float x1) {
    __half2 p = __halves2half2(__float2half_rn(x0), __float2half_rn(x1));
    return *(uint32_t*)&p;
}

// ---------------------------------------------------------------------------
// Merged fp32 -> fp16 convert kernel: all 5 regions in one launch.
// ---------------------------------------------------------------------------
#define NQ_X  (MTOT * DD / 4)
#define NQ_WQ (DD * DD / 4)
#define NQ_WK (DKV * DD / 4)
#define NQ_ALL (NQ_X + NQ_WQ + 2 * NQ_WK + NQ_WQ)

__global__ __launch_bounds__(256)
void conv_all_kernel(const float* __restrict__ x,  const float* __restrict__ Wq,
                     const float* __restrict__ Wk, const float* __restrict__ Wv,
                     const float* __restrict__ Wo,
                     __half* __restrict__ xh, __half* __restrict__ wqkv,
                     __half* __restrict__ wo)
{
    int i = blockIdx.x * blockDim.x + threadIdx.x;
    if (i >= NQ_ALL) return;
    const float* src;
    __half* dst;
    int j = i;
    if (j < NQ_X)                 { src = x;  dst = xh; }
    else if ((j -= NQ_X) < NQ_WQ) { src = Wq; dst = wqkv; }
    else if ((j -= NQ_WQ) < NQ_WK){ src = Wk; dst = wqkv + (size_t)DD * DD; }
    else if ((j -= NQ_WK) < NQ_WK){ src = Wv; dst = wqkv + (size_t)(DD + DKV) * DD; }
    else { j -= NQ_WK;             src = Wo; dst = wo; }
    float4 v = ((const float4*)src)[j];
    ((uint2*)dst)[j] = make_uint2(pack_h2(v.x, v.y), pack_h2(v.z, v.w));
}

// ---------------------------------------------------------------------------
// fp16 1-pass GEMM:  C = A * B^T
// CTA 128x128, BK=64, 3-stage cp.async (96KB), one barrier per chunk.
// 256 threads = 8 warps (2x4), warp tile 64x32.
// __launch_bounds__(256, 2): 128-reg cap, 2 CTAs/SM.
// ---------------------------------------------------------------------------
#define GSTAGES   3
#define GTILE_B   16384
#define GSTAGE_B  (2 * GTILE_B)             // 32 KB
#define GEMM_SMEM (GSTAGES * GSTAGE_B)      // 96 KB

template<int MODE>
__global__ __launch_bounds__(256, 2)
void gemm_tc_kernel(const __half* __restrict__ Ah, const __half* __restrict__ Bh,
                    float* __restrict__ C,
                    __half* __restrict__ Qo, __half* __restrict__ Ko, __half* __restrict__ Vo,
                    int M, int N, int K)
{
    extern __shared__ __align__(128) char smem[];
    const uint32_t sbase = s2u(smem);

    const int tid = threadIdx.x;
    const int wid = tid >> 5;
    const int lane = tid & 31;
    const int bm = blockIdx.y * 128;
    const int bn = blockIdx.x * 128;

    const int wm = (wid & 1) * 64;
    const int wn = (wid >> 1) * 32;

    const size_t rowstride = (size_t)K * 2;
    const int NC = K >> 6;

    auto load_chunk = [&](int c, int s) {
        const uint32_t sb = sbase + s * GSTAGE_B;
        const size_t k0b = (size_t)c * 128;
#pragma unroll
        for (int t = 0; t < 2; t++) {
            const int rbase = t ? bn : bm;
            const char* src = (const char*)(t ? Bh : Ah);
#pragma unroll
            for (int j = 0; j < 4; j++) {
                int i = tid + j * 256;
                int r = i >> 3;
                int ck = i & 7;
                const char* ga = src + (size_t)(rbase + r) * rowstride + k0b + ck * 16;
                CP16(sw128(sb + t * GTILE_B, r, ck), ga);
            }
        }
    };

    float acc[4][4][4];
#pragma unroll
    for (int i = 0; i < 4; i++)
#pragma unroll
        for (int j = 0; j < 4; j++)
#pragma unroll
            for (int q = 0; q < 4; q++) acc[i][j][q] = 0.f;

    load_chunk(0, 0); CPCOMMIT();
    load_chunk(1, 1); CPCOMMIT();

    for (int c = 0; c < NC; c++) {
        const int s = c % GSTAGES;
        CPWAIT(1);
        __syncthreads();

        if (c + 2 < NC) {
            load_chunk(c + 2, (c + 2) % GSTAGES);
            CPCOMMIT();
        }

        const uint32_t sA = sbase + s * GSTAGE_B;
        const uint32_t sB = sA + GTILE_B;

#pragma unroll
        for (int ks = 0; ks < 4; ks++) {
            uint32_t af[4][4], bf[4][2];
            {
                int ar = (lane & 15);
                int ac = 2 * ks + (lane >> 4);
#pragma unroll
                for (int fm = 0; fm < 4; fm++) {
                    uint32_t ad = sw128(sA, wm + fm * 16 + ar, ac);
                    LDSM4(af[fm][0], af[fm][1], af[fm][2], af[fm][3], ad);
                }
                int br = (lane & 7);
                int bsel = (lane >> 4);
                int bc = 2 * ks + ((lane >> 3) & 1);
#pragma unroll
                for (int fp = 0; fp < 2; fp++) {
                    uint32_t bd = sw128(sB, wn + (fp * 2 + bsel) * 8 + br, bc);
                    uint32_t t0, t1, t2, t3;
                    LDSM4(t0, t1, t2, t3, bd);
                    bf[fp * 2][0] = t0; bf[fp * 2][1] = t1;
                    bf[fp * 2 + 1][0] = t2; bf[fp * 2 + 1][1] = t3;
                }
            }

#pragma unroll
            for (int fm = 0; fm < 4; fm++)
#pragma unroll
                for (int fn = 0; fn < 4; fn++)
                    MMAH16816(acc[fm][fn], af[fm], bf[fn]);
        }
    }

    const int lr = lane >> 2;
    const int lc = (lane & 3) * 2;
#pragma unroll
    for (int fm = 0; fm < 4; fm++) {
#pragma unroll
        for (int fn = 0; fn < 4; fn++) {
            int r0 = bm + wm + fm * 16 + lr;
            int cc = bn + wn + fn * 8 + lc;
            if (MODE == 0) {
                if (bn < DD) {
                    *(uint32_t*)&Qo[(size_t)r0 * DD + cc] =
                        pack_h2(acc[fm][fn][0], acc[fm][fn][1]);
                    *(uint32_t*)&Qo[(size_t)(r0 + 8) * DD + cc] =
                        pack_h2(acc[fm][fn][2], acc[fm][fn][3]);
                } else if (bn < DD + DKV) {
                    int kc = cc - DD;
                    *(uint32_t*)&Ko[(size_t)r0 * DKV + kc] =
                        pack_h2(acc[fm][fn][0], acc[fm][fn][1]);
                    *(uint32_t*)&Ko[(size_t)(r0 + 8) * DKV + kc] =
                        pack_h2(acc[fm][fn][2], acc[fm][fn][3]);
                } else {
                    int vc = cc - DD - DKV;
                    *(uint32_t*)&Vo[(size_t)r0 * DKV + vc] =
                        pack_h2(acc[fm][fn][0], acc[fm][fn][1]);
                    *(uint32_t*)&Vo[(size_t)(r0 + 8) * DKV + vc] =
                        pack_h2(acc[fm][fn][2], acc[fm][fn][3]);
                }
            } else {
                *(float2*)&C[(size_t)r0 * N + cc]       = make_float2(acc[fm][fn][0], acc[fm][fn][1]);
                *(float2*)&C[(size_t)(r0 + 8) * N + cc] = make_float2(acc[fm][fn][2], acc[fm][fn][3]);
            }
        }
    }
}

// ---------------------------------------------------------------------------
// Tensor-core flash attention (fp16 1-pass).
// LPT scheduling: qt = (T/128 - 1) - blockIdx.x (heavy tiles first).
// __launch_bounds__(256, 2). 8 warps x 16 q-rows. KV tile 64, 3-stage ring.
// ---------------------------------------------------------------------------
#define QTILE_B   16384
#define KVSUB_B   8192
#define FSTAGE_B  (2 * KVSUB_B)
#define FSTAGES   3
#define FLASH_SMEM (QTILE_B + FSTAGES * FSTAGE_B)

__global__ __launch_bounds__(256, 2)
void flash_tc_kernel()
{
    extern __shared__ __align__(128) char fsm[];
    const uint32_t sbase = s2u(fsm);
    const uint32_t QT = sbase;
    const uint32_t STG0 = sbase + QTILE_B;

    const int qt  = (TT / 128 - 1) - blockIdx.x;   // heavy tiles first
    const int h   = blockIdx.y;
    const int b   = blockIdx.z;
    const int kvh = h >> 2;
    const int qb  = qt * 128;

    const int tid = threadIdx.x;
    const int wid = tid >> 5;
    const int lane = tid & 31;

    // ---- load Q tile ----
#pragma unroll
    for (int j = 0; j < 4; j++) {
        int i = tid + j * 256;
        int r = i >> 3;
        int ck = i & 7;
        size_t e = (size_t)(b * TT + qb + r) * DD + h * HD + ck * 8;
        CP16(sw128(QT, r, ck), (const char*)&g_Q[e]);
    }
    CPCOMMIT();

    auto load_kv = [&](int kt, int s) {
        const uint32_t sb = STG0 + s * FSTAGE_B;
#pragma unroll
        for (int j = 0; j < 2; j++) {
            int i = tid + j * 256;
            int r = i >> 3;
            int ck = i & 7;
            size_t e = (size_t)(b * TT + kt * 64 + r) * DKV + kvh * HD + ck * 8;
            uint32_t so = sw128(sb, r, ck);
            CP16(so,           (const char*)&g_K[e]);
            CP16(so + KVSUB_B, (const char*)&g_V[e]);
        }
    };

    const int NT = 2 * (qt + 1);

    load_kv(0, 0); CPCOMMIT();
    if (NT > 1) { load_kv(1, 1); CPCOMMIT(); }

    CPWAIT(2);
    __syncthreads();

    // ---- Q fragments (register-resident) ----
    uint32_t qF[4][4];
    {
        int ar = lane & 15;
        int ac = lane >> 4;
#pragma unroll
        for (int ks = 0; ks < 4; ks++) {
            uint32_t ad = sw128(QT, wid * 16 + ar, 2 * ks + ac);
            LDSM4(qF[ks][0], qF[ks][1], qF[ks][2], qF[ks][3], ad);
        }
    }

    float oacc[8][4];
#pragma unroll
    for (int i = 0; i < 8; i++)
#pragma unroll
        for (int q = 0; q < 4; q++) oacc[i][q] = 0.f;
    float mrow[2] = {-1e30f, -1e30f};
    float lrow[2] = {0.f, 0.f};

    const int wr = qb + wid * 16;
    const float scale = 0.125f;

    for (int kt = 0; kt < NT; kt++) {
        const int s = kt % FSTAGES;
        const int kb = kt * 64;

        CPWAIT(1);
        __syncthreads();

        if (kt + 2 < NT) {
            load_kv(kt + 2, (kt + 2) % FSTAGES);
            CPCOMMIT();
        }

        const uint32_t KH = STG0 + s * FSTAGE_B;
        const uint32_t VH = KH + KVSUB_B;

        // ---- S = Q K^T ----
        float sacc[8][4];
#pragma unroll
        for (int i = 0; i < 8; i++)
#pragma unroll
            for (int q = 0; q < 4; q++) sacc[i][q] = 0.f;

        {
            int br = lane & 7;
            int bsel = lane >> 4;
            int bksel = (lane >> 3) & 1;
#pragma unroll
            for (int ks = 0; ks < 4; ks++) {
                int bc = 2 * ks + bksel;
#pragma unroll
                for (int fp = 0; fp < 4; fp++) {
                    int krow = fp * 16 + bsel * 8 + br;
                    uint32_t t0, t1, t2, t3;
                    LDSM4(t0, t1, t2, t3, sw128(KH, krow, bc));
                    MMAH16816R(sacc[2 * fp],     qF[ks], t0, t1);
                    MMAH16816R(sacc[2 * fp + 1], qF[ks], t2, t3);
                }
            }
        }

        // ---- scale + causal mask ----
        const bool need_mask = (kb + 63 > wr);
#pragma unroll
        for (int fn = 0; fn < 8; fn++)
#pragma unroll
            for (int q = 0; q < 4; q++) sacc[fn][q] *= scale;
        if (need_mask) {
#pragma unroll
            for (int fn = 0; fn < 8; fn++)
#pragma unroll
                for (int q = 0; q < 4; q++) {
                    int kc = kb + fn * 8 + (lane & 3) * 2 + (q & 1);
                    int qr = wr + (lane >> 2) + (q >> 1) * 8;
                    if (kc > qr) sacc[fn][q] = -1e30f;
                }
        }

        // ---- online softmax ----
#pragma unroll
        for (int r = 0; r < 2; r++) {
            float rmax = -1e30f;
#pragma unroll
            for (int fn = 0; fn < 8; fn++) {
                rmax = fmaxf(rmax, sacc[fn][2 * r]);
                rmax = fmaxf(rmax, sacc[fn][2 * r + 1]);
            }
            rmax = fmaxf(rmax, __shfl_xor_sync(0xffffffffu, rmax, 1));
            rmax = fmaxf(rmax, __shfl_xor_sync(0xffffffffu, rmax, 2));

            float mn = fmaxf(mrow[r], rmax);
            float alpha = __expf(mrow[r] - mn);
            mrow[r] = mn;

            float rs = 0.f;
#pragma unroll
            for (int fn = 0; fn < 8; fn++) {
                float p0 = __expf(sacc[fn][2 * r] - mn);
                float p1 = __expf(sacc[fn][2 * r + 1] - mn);
                sacc[fn][2 * r] = p0;
                sacc[fn][2 * r + 1] = p1;
                rs += p0 + p1;
            }
            rs += __shfl_xor_sync(0xffffffffu, rs, 1);
            rs += __shfl_xor_sync(0xffffffffu, rs, 2);
            lrow[r] = lrow[r] * alpha + rs;

#pragma unroll
            for (int fn = 0; fn < 8; fn++) {
                oacc[fn][2 * r]     *= alpha;
                oacc[fn][2 * r + 1] *= alpha;
            }
        }

        // ---- O += P V ----
        {
            int g = lane >> 3;
            int vr_off = (g & 1) * 8 + (lane & 7);
            int vc_off = g >> 1;
#pragma unroll
            for (int ks = 0; ks < 4; ks++) {
                uint32_t pF[4];
                pF[0] = pack_h2(sacc[2 * ks][0],     sacc[2 * ks][1]);
                pF[1] = pack_h2(sacc[2 * ks][2],     sacc[2 * ks][3]);
                pF[2] = pack_h2(sacc[2 * ks + 1][0], sacc[2 * ks + 1][1]);
                pF[3] = pack_h2(sacc[2 * ks + 1][2], sacc[2 * ks + 1][3]);

                int vrow = ks * 16 + vr_off;
#pragma unroll
                for (int fv = 0; fv < 4; fv++) {
                    int vchunk = 2 * fv + vc_off;
                    uint32_t t0, t1, t2, t3;
                    LDSM4T(t0, t1, t2, t3, sw128(VH, vrow, vchunk));
                    MMAH16816R(oacc[2 * fv],     pF, t0, t1);
                    MMAH16816R(oacc[2 * fv + 1], pF, t2, t3);
                }
            }
        }
    }

    // ---- epilogue: normalize, fp16 store ----
#pragma unroll
    for (int r = 0; r < 2; r++) {
        float inv = 1.f / lrow[r];
        int row = wr + (lane >> 2) + 8 * r;
#pragma unroll
        for (int fn = 0; fn < 8; fn++) {
            int col = h * HD + fn * 8 + (lane & 3) * 2;
            float x0 = oacc[fn][2 * r] * inv;
            float x1 = oacc[fn][2 * r + 1] * inv;
            size_t e = (size_t)(b * TT + row) * DD + col;
            *(uint32_t*)&g_A[e] = pack_h2(x0, x1);
        }
    }
}

// ---------------------------------------------------------------------------
// Launch
// ---------------------------------------------------------------------------
extern "C" void kernel_launch(void* const* d_in, const int* in_sizes, int n_in,
                              void* d_out, int out_size)
{
    const float* x  = (const float*)d_in[0];
    const float* Wq = (const float*)d_in[1];
    const float* Wk = (const float*)d_in[2];
    const float* Wv = (const float*)d_in[3];
    const float* Wo = (const float*)d_in[4];
    float* out = (float*)d_out;

    __half *xh, *wqkv, *wo, *qh, *kh, *vh, *ah;
    cudaGetSymbolAddress((void**)&xh, g_x);
    cudaGetSymbolAddress((void**)&wqkv, g_Wqkv);
    cudaGetSymbolAddress((void**)&wo, g_Wo);
    cudaGetSymbolAddress((void**)&qh, g_Q);
    cudaGetSymbolAddress((void**)&kh, g_K);
    cudaGetSymbolAddress((void**)&vh, g_V);
    cudaGetSymbolAddress((void**)&ah, g_A);

    cudaFuncSetAttribute(gemm_tc_kernel<0>,
                         cudaFuncAttributeMaxDynamicSharedMemorySize, GEMM_SMEM);
    cudaFuncSetAttribute(gemm_tc_kernel<1>,
                         cudaFuncAttributeMaxDynamicSharedMemorySize, GEMM_SMEM);
    cudaFuncSetAttribute(flash_tc_kernel,
                         cudaFuncAttributeMaxDynamicSharedMemorySize, FLASH_SMEM);

    // Merged fp32 -> fp16 converts (one launch)
    conv_all_kernel<<<(NQ_ALL + 255) / 256, 256>>>(x, Wq, Wk, Wv, Wo, xh, wqkv, wo);

    // Merged QKV projection (fp16 1-pass, BK=64, 64x32 warp tiles, 2 CTAs/SM)
    gemm_tc_kernel<0><<<dim3(NQKV / 128, MTOT / 128), 256, GEMM_SMEM>>>(
        xh, wqkv, nullptr, qh, kh, vh, MTOT, NQKV, DD);

    // fp16 1-pass causal GQA flash attention (LPT order, 2 CTAs/SM)
    flash_tc_kernel<<<dim3(TT / 128, HH, BB), 256, FLASH_SMEM>>>();

    // Output projection (fp16 1-pass, BK=64, 64x32 warp tiles, 2 CTAs/SM)
    gemm_tc_kernel<1><<<dim3(DD / 128, MTOT / 128), 256, GEMM_SMEM>>>(
        ah, wo, out, nullptr, nullptr, nullptr, MTOT, DD, DD);
}